// round 16
// baseline (speedup 1.0000x reference)
#include <cuda_runtime.h>
#include <cuda_fp16.h>
#include <math.h>
#include <stdint.h>

// Problem constants
#define HDIM   2880
#define NHEADS 64
#define NKV    8
#define DHEAD  64
#define GRP    8          // NHEADS / NKV
#define WIN    128
#define QKVW   5120       // (NHEADS + 2*NKV) * DHEAD
#define AOW    4096       // NHEADS * DHEAD
#define NMAX   1024

// Scratch (device globals: allocation-free)
__device__ __align__(16) __half g_qkvh[NMAX * QKVW];  // fp16 qkv (10 MB)
__device__ int   g_positions[NMAX];
__device__ float g_cs[NMAX * 32 * 2];  // interleaved cos/sin per (tok, j)

__device__ __align__(16) __half g_ah[NMAX * HDIM];    // fp16 hidden states
__device__ __align__(16) __half g_ath[NMAX * AOW];    // fp16 attn output
__device__ __align__(16) __half g_wq[HDIM * QKVW];    // fp16 Wqkv
__device__ __align__(16) __half g_wo[AOW * HDIM];     // fp16 Wo
__device__ __align__(16) __half g_qb[NMAX * AOW];           // roped+scaled Q fp16
__device__ __align__(16) __half g_kb[NMAX * NKV * DHEAD];   // roped K fp16 (1 MB)
__device__ __align__(16) __half g_vb[NMAX * NKV * DHEAD];   // V fp16 (1 MB)

// ---------------------------------------------------------------------------
// positions normalizer + RoPE cos/sin table (fused, multi-block).
// ---------------------------------------------------------------------------
__global__ void pos_table_kernel(const void* __restrict__ pos_raw, int n)
{
    const long long* p64 = (const long long*)pos_raw;
    const int*       p32 = (const int*)pos_raw;

    __shared__ int is64;
    if (threadIdx.x == 0) {
        long long v0 = p64[0];
        long long v1 = (n > 1) ? p64[1] : 1;
        is64 = (v0 == 0 && v1 == 1) ? 1 : 0;
    }
    __syncthreads();

    int idx = blockIdx.x * blockDim.x + threadIdx.x;
    if (idx >= n * 32) return;

    int tok = idx >> 5;
    int j   = idx & 31;

    int p = is64 ? (int)p64[tok] : p32[tok];
    if (j == 0) g_positions[tok] = p;

    float inv_freq = powf(150000.0f, -((float)j) / 32.0f);
    float s, c;
    sincosf((float)p * inv_freq, &s, &c);
    g_cs[idx * 2]     = c;
    g_cs[idx * 2 + 1] = s;
}

// ---------------------------------------------------------------------------
// fused fp32 -> fp16 conversion of hs, Wqkv, Wo; 8 independent elems/thread.
// ---------------------------------------------------------------------------
__device__ __forceinline__ void cvt4(const float* __restrict__ s,
                                     __half* __restrict__ d, int i)
{
    float4 v = ((const float4*)s)[i];
    __half2 p0 = __halves2half2(__float2half(v.x), __float2half(v.y));
    __half2 p1 = __halves2half2(__float2half(v.z), __float2half(v.w));
    uint2 o;
    o.x = *(uint32_t*)&p0; o.y = *(uint32_t*)&p1;
    ((uint2*)d)[i] = o;
}

__global__ void cvt_all_kernel(const float* __restrict__ hs,
                               const float* __restrict__ wqkv,
                               const float* __restrict__ wo,
                               __half* __restrict__ ah,
                               __half* __restrict__ wq,
                               __half* __restrict__ wo16,
                               int n4_hs, int n4_wq, int n4_wo, int stride)
{
    int base = blockIdx.x * blockDim.x + threadIdx.x;
    int tot = n4_hs + n4_wq + n4_wo;
    #pragma unroll
    for (int q = 0; q < 8; q++) {
        int i = base + q * stride;
        if (i >= tot) break;
        if (i < n4_hs) { cvt4(hs, ah, i); continue; }
        int i2 = i - n4_hs;
        if (i2 < n4_wq) { cvt4(wqkv, wq, i2); continue; }
        cvt4(wo, wo16, i2 - n4_wq);
    }
}

// ---------------------------------------------------------------------------
// MMA helpers
// ---------------------------------------------------------------------------
__device__ __forceinline__ uint32_t smem_u32(const void* p) {
    return (uint32_t)__cvta_generic_to_shared(p);
}
__device__ __forceinline__ void ldsm_x4(uint32_t* r, uint32_t addr) {
    asm volatile("ldmatrix.sync.aligned.m8n8.x4.shared.b16 {%0,%1,%2,%3}, [%4];"
        : "=r"(r[0]), "=r"(r[1]), "=r"(r[2]), "=r"(r[3]) : "r"(addr));
}
__device__ __forceinline__ void ldsm_x4_t(uint32_t* r, uint32_t addr) {
    asm volatile("ldmatrix.sync.aligned.m8n8.x4.trans.shared.b16 {%0,%1,%2,%3}, [%4];"
        : "=r"(r[0]), "=r"(r[1]), "=r"(r[2]), "=r"(r[3]) : "r"(addr));
}
__device__ __forceinline__ void mma_fp16(float* d, const uint32_t* a, const uint32_t* b) {
    asm volatile(
        "mma.sync.aligned.m16n8k16.row.col.f32.f16.f16.f32 "
        "{%0,%1,%2,%3}, {%4,%5,%6,%7}, {%8,%9}, {%0,%1,%2,%3};"
        : "+f"(d[0]), "+f"(d[1]), "+f"(d[2]), "+f"(d[3])
        : "r"(a[0]), "r"(a[1]), "r"(a[2]), "r"(a[3]), "r"(b[0]), "r"(b[1]));
}
__device__ __forceinline__ void cp16(uint32_t dst, const void* src) {
    asm volatile("cp.async.cg.shared.global [%0], [%1], 16;"
        :: "r"(dst), "l"(src));
}

// ---------------------------------------------------------------------------
// 1-pass fp16 GEMM, 3-stage cp.async pipeline, 2 CTAs/SM (R10-proven).
// HALF_OUT selects fp16 vs fp32 output.
// ---------------------------------------------------------------------------
extern __shared__ char dsm[];

template<int TN_, bool HALF_OUT>
__global__ __launch_bounds__(TN_ * 2, 2) void gemm1p_kernel(
    const __half* __restrict__ A, const __half* __restrict__ B,
    void* __restrict__ Cv, int M, int N, int K)
{
    constexpr int NT   = TN_ * 2;
    constexpr int SKB_ = TN_ + 8;
    constexpr uint32_t OFF_B = 10240;                  // A: 128 rows x 80B
    constexpr uint32_t STG   = 10240u + 32u * SKB_ * 2u;
    constexpr int BGRAN = 32 * (TN_ / 8);

    const int tid  = threadIdx.x;
    const int wid  = tid >> 5;
    const int lane = tid & 31;
    const int m0 = blockIdx.y * 128;
    const int n0 = blockIdx.x * TN_;

    const int wm = (wid & 1) * 64;
    const int wn = (wid >> 1) * 32;

    const uint32_t sb = smem_u32(dsm);

    float acc[4][4][4];
    #pragma unroll
    for (int i = 0; i < 4; i++)
        #pragma unroll
        for (int j = 0; j < 4; j++)
            #pragma unroll
            for (int k = 0; k < 4; k++) acc[i][j][k] = 0.0f;

    const int nk = K / 32;

    auto issue = [&](int slot, int kc) {
        const uint32_t s = sb + (uint32_t)slot * STG;
        #pragma unroll 2
        for (int i = tid; i < 512; i += NT) {
            int r = i >> 2, c = i & 3;
            uint32_t off = (uint32_t)(r * 80 + c * 16);
            size_t g = (size_t)(m0 + r) * K + (size_t)kc * 32 + c * 8;
            cp16(s + off, A + g);
        }
        #pragma unroll 2
        for (int i = tid; i < BGRAN; i += NT) {
            int r = i / (TN_ / 8), c = i % (TN_ / 8);
            uint32_t off = (uint32_t)(r * (SKB_ * 2) + c * 16);
            size_t g = (size_t)(kc * 32 + r) * N + n0 + c * 8;
            cp16(s + OFF_B + off, B + g);
        }
    };

    issue(0, 0);
    asm volatile("cp.async.commit_group;");
    if (nk > 1) issue(1, 1);
    asm volatile("cp.async.commit_group;");

    const int lm_row = lane & 15;
    const int lm_kch = (lane >> 4) * 8;

    int slot = 0;
    for (int kt = 0; kt < nk; kt++) {
        if (kt + 2 < nk) {
            int ps = slot + 2; if (ps >= 3) ps -= 3;
            issue(ps, kt + 2);
        }
        asm volatile("cp.async.commit_group;");
        asm volatile("cp.async.wait_group 2;");
        __syncthreads();

        const uint32_t stg = sb + (uint32_t)slot * STG;

        #pragma unroll
        for (int ks = 0; ks < 2; ks++) {
            const int k0 = ks * 16;
            uint32_t ah[4][4], bb[2][4];
            #pragma unroll
            for (int mi = 0; mi < 4; mi++) {
                uint32_t off = (uint32_t)((wm + mi * 16 + lm_row) * 80
                                          + (k0 + lm_kch) * 2);
                ldsm_x4(ah[mi], stg + off);
            }
            #pragma unroll
            for (int np = 0; np < 2; np++) {
                uint32_t off = (uint32_t)((k0 + lm_row) * (SKB_ * 2)
                                          + (wn + np * 16 + lm_kch) * 2);
                ldsm_x4_t(bb[np], stg + OFF_B + off);
            }
            #pragma unroll
            for (int mi = 0; mi < 4; mi++) {
                #pragma unroll
                for (int nj = 0; nj < 4; nj++) {
                    const uint32_t* bp = &bb[nj >> 1][(nj & 1) * 2];
                    mma_fp16(acc[mi][nj], ah[mi], bp);
                }
            }
        }
        __syncthreads();
        slot++; if (slot >= 3) slot = 0;
    }

    const int er = lane >> 2;
    const int ec = (lane & 3) * 2;
    #pragma unroll
    for (int mi = 0; mi < 4; mi++) {
        #pragma unroll
        for (int nj = 0; nj < 4; nj++) {
            const int row = m0 + wm + mi * 16 + er;
            const int col = n0 + wn + nj * 8 + ec;
            if (HALF_OUT) {
                __half* C = (__half*)Cv;
                *(__half2*)&C[(size_t)row * N + col] =
                    __floats2half2_rn(acc[mi][nj][0], acc[mi][nj][1]);
                *(__half2*)&C[(size_t)(row + 8) * N + col] =
                    __floats2half2_rn(acc[mi][nj][2], acc[mi][nj][3]);
            } else {
                float* C = (float*)Cv;
                float2 v01; v01.x = acc[mi][nj][0]; v01.y = acc[mi][nj][1];
                float2 v23; v23.x = acc[mi][nj][2]; v23.y = acc[mi][nj][3];
                *(float2*)&C[(size_t)row * N + col]       = v01;
                *(float2*)&C[(size_t)(row + 8) * N + col] = v23;
            }
        }
    }
}

#define SMEM_T64 (3 * (10240 + 32 * 72 * 2))    // 44544
#define SMEM_T96 (3 * (10240 + 32 * 104 * 2))   // 50688

// ---------------------------------------------------------------------------
// RoPE + compact fp16 emission from fp16 qkv:
// q roped+scaled -> qb; k roped -> kb; v copied -> vb.
// ---------------------------------------------------------------------------
__global__ void rope_kv_kernel(const __half* __restrict__ qkv,
                               __half* __restrict__ qb,
                               __half* __restrict__ kb,
                               __half* __restrict__ vb, int n)
{
    int idx = blockIdx.x * blockDim.x + threadIdx.x;
    const int nrope = n * (NHEADS + NKV) * 32;

    if (idx < nrope) {
        int j   = idx & 31;
        int h   = (idx >> 5) % (NHEADS + NKV);
        int tok = idx / ((NHEADS + NKV) * 32);

        float2 cs = *(const float2*)&g_cs[(tok * 32 + j) * 2];

        if (h < NHEADS) {
            const __half* base = qkv + (size_t)tok * QKVW + h * DHEAD;
            float x1 = __half2float(base[j]);
            float x2 = __half2float(base[j + 32]);
            __half* qo = qb + (size_t)tok * AOW + h * DHEAD;
            qo[j]      = __float2half((x1 * cs.x - x2 * cs.y) * 0.125f);
            qo[j + 32] = __float2half((x2 * cs.x + x1 * cs.y) * 0.125f);
        } else {
            int kh = h - NHEADS;
            const __half* base = qkv + (size_t)tok * QKVW + NHEADS * DHEAD
                               + (size_t)kh * DHEAD;
            float x1 = __half2float(base[j]);
            float x2 = __half2float(base[j + 32]);
            __half* ko = kb + ((size_t)tok * NKV + kh) * DHEAD;
            ko[j]      = __float2half(x1 * cs.x - x2 * cs.y);
            ko[j + 32] = __float2half(x2 * cs.x + x1 * cs.y);
        }
        return;
    }

    int iv = idx - nrope;                       // v half2 pairs (copy)
    int totv = n * NKV * DHEAD / 2;             // n*256
    if (iv >= totv) return;
    int tok = iv >> 8;
    int r   = (iv & 255) * 2;
    *(__half2*)&vb[(size_t)tok * (NKV * DHEAD) + r] =
        *(const __half2*)(qkv + (size_t)tok * QKVW + (NHEADS + NKV) * DHEAD + r);
}

// ---------------------------------------------------------------------------
// HMMA sliding-window attention with sinks, 4 tokens per block, fp16 inputs.
// Softmax probs via ex2.approx.f16x2 (h2exp2): 2 exps per MUFU op.
// ---------------------------------------------------------------------------
#define UNI 131
#define ATTN_SMEM 56448
#define LOG2E 1.4426950408889634f

__global__ __launch_bounds__(256) void attn_kernel(
    const __half* __restrict__ qb, const __half* __restrict__ kb,
    const __half* __restrict__ vb, const float* __restrict__ sinks,
    __half* __restrict__ out16, int n)
{
    __half* Kh  = (__half*)dsm;               // [144][72]
    float*  S   = (float*)dsm;                // [144][36] (aliases Kh)
    __half* Qd  = (__half*)(dsm + 20736);     // [64][40]
    __half* Ps  = (__half*)(dsm + 25856);     // [32][152]
    __half* Vh  = (__half*)(dsm + 35584);     // [144][72]
    float*  dinv = (float*)(dsm + 56320);     // [32]

    const int tok0 = blockIdx.x * 4;
    const int kv   = blockIdx.y;
    const int tid  = threadIdx.x;
    const int lane = tid & 31;
    const int wid  = tid >> 5;

    const int p0 = g_positions[tok0];

    const uint32_t khb = smem_u32(Kh);
    const uint32_t vhb = smem_u32(Vh);

    // --- K/V window fill via cp.async (131 rows x 8 granules each) ---
    for (int i = tid; i < UNI * 8; i += 256) {
        int u  = i >> 3;
        int c8 = (i & 7) << 3;
        int t = p0 - (WIN - 1) + u;
        t = max(0, min(t, n - 1));
        size_t src = ((size_t)t * NKV + kv) * DHEAD + c8;
        uint32_t off = (uint32_t)(u * 72 + c8) * 2;
        cp16(khb + off, kb + src);
        cp16(vhb + off, vb + src);
    }
    asm volatile("cp.async.commit_group;");

    // --- Q transpose copy [d][p], fp16 ---
    for (int i = tid; i < 32 * 64; i += 256) {
        int p = i & 31, d = i >> 5;
        Qd[d * 40 + p] = qb[(size_t)(tok0 + (p >> 3)) * AOW
                            + ((size_t)kv * 8 + (p & 7)) * DHEAD + d];
    }

    // --- zero pad rows 131..143 of Kh, Vh ---
    {
        uint4 z; z.x = 0; z.y = 0; z.z = 0; z.w = 0;
        for (int i = tid; i < 13 * 8; i += 256) {
            int u  = UNI + (i >> 3);
            int c8 = (i & 7) << 3;
            *(uint4*)&Kh[u * 72 + c8] = z;
            *(uint4*)&Vh[u * 72 + c8] = z;
        }
    }

    asm volatile("cp.async.wait_group 0;");
    __syncthreads();

    const int lm_row = lane & 15;
    const int lm_kch = (lane >> 4) * 8;
    const int er = lane >> 2;
    const int ec = (lane & 3) * 2;

    const uint32_t qdb = smem_u32(Qd);

    // --- score MMAs: warp w handles m-tile w; warp 0 also m-tile 8 ---
    float sacc[2][4][4];
    #pragma unroll
    for (int z = 0; z < 2; z++)
        #pragma unroll
        for (int nj = 0; nj < 4; nj++)
            #pragma unroll
            for (int q = 0; q < 4; q++) sacc[z][nj][q] = 0.0f;

    const int nmt = (wid == 0) ? 2 : 1;
    for (int z = 0; z < nmt; z++) {
        const int mt = (z == 0) ? wid : 8;
        #pragma unroll
        for (int kk = 0; kk < 4; kk++) {
            uint32_t a[4], bb[2][4];
            ldsm_x4(a, khb + (uint32_t)((mt * 16 + lm_row) * 72
                                        + kk * 16 + lm_kch) * 2);
            #pragma unroll
            for (int np = 0; np < 2; np++)
                ldsm_x4_t(bb[np], qdb + (uint32_t)((kk * 16 + lm_row) * 40
                                                   + np * 16 + lm_kch) * 2);
            #pragma unroll
            for (int nj = 0; nj < 4; nj++)
                mma_fp16(sacc[z][nj], a, &bb[nj >> 1][(nj & 1) * 2]);
        }
    }
    __syncthreads();   // all warps done reading Kh before S overwrites it

    // --- store S fragments; zero Ps ---
    for (int z = 0; z < nmt; z++) {
        const int mt = (z == 0) ? wid : 8;
        #pragma unroll
        for (int nj = 0; nj < 4; nj++) {
            int u0 = mt * 16 + er;
            int c  = nj * 8 + ec;
            float2 v01; v01.x = sacc[z][nj][0]; v01.y = sacc[z][nj][1];
            float2 v23; v23.x = sacc[z][nj][2]; v23.y = sacc[z][nj][3];
            *(float2*)&S[u0 * 36 + c]       = v01;
            *(float2*)&S[(u0 + 8) * 36 + c] = v23;
        }
    }
    for (int i = tid; i < 32 * 152 / 2; i += 256)
        ((uint32_t*)Ps)[i] = 0;
    __syncthreads();

    // --- softmax with sinks: warp wid handles pairs p = 4*wid .. 4*wid+3.
    //     probs via ex2.approx.f16x2 (2 exps per MUFU op). ---
    #pragma unroll
    for (int pp = 0; pp < 4; pp++) {
        int p = (wid << 2) + pp;
        int j = p >> 3, g = p & 7;
        float vals[4];
        #pragma unroll
        for (int i = 0; i < 4; i++) {
            int u = j + lane + i * 32;
            bool tvalid = (p0 - (WIN - 1) + u) >= 0;
            vals[i] = tvalid ? S[u * 36 + p] : -INFINITY;
        }
        float m = fmaxf(fmaxf(vals[0], vals[1]), fmaxf(vals[2], vals[3]));
        #pragma unroll
        for (int off = 16; off; off >>= 1)
            m = fmaxf(m, __shfl_xor_sync(0xffffffffu, m, off));
        float snk = sinks[kv * GRP + g];
        m = fmaxf(m, snk);

        __half2 h01 = h2exp2(__floats2half2_rn((vals[0] - m) * LOG2E,
                                               (vals[1] - m) * LOG2E));
        __half2 h23 = h2exp2(__floats2half2_rn((vals[2] - m) * LOG2E,
                                               (vals[3] - m) * LOG2E));
        Ps[p * 152 + (j + lane)]      = __low2half(h01);
        Ps[p * 152 + (j + lane + 32)] = __high2half(h01);
        Ps[p * 152 + (j + lane + 64)] = __low2half(h23);
        Ps[p * 152 + (j + lane + 96)] = __high2half(h23);

        float2 f01 = __half22float2(h01);
        float2 f23 = __half22float2(h23);
        float ssum = f01.x + f01.y + f23.x + f23.y;
        #pragma unroll
        for (int off = 16; off; off >>= 1)
            ssum += __shfl_xor_sync(0xffffffffu, ssum, off);
        if (lane == 0)
            dinv[p] = 1.0f / (ssum + __expf(snk - m));
    }
    __syncthreads();

    // --- PV MMAs: warp w -> m-tile (w&1), d cols (w>>1)*16 .. +15 ---
    const uint32_t psb = smem_u32(Ps);
    const int mi = wid & 1;
    const int wn = (wid >> 1) * 16;

    float oacc[2][4];
    #pragma unroll
    for (int nj = 0; nj < 2; nj++)
        #pragma unroll
        for (int q = 0; q < 4; q++) oacc[nj][q] = 0.0f;

    #pragma unroll
    for (int kk = 0; kk < 9; kk++) {
        uint32_t a[4], bb[4];
        ldsm_x4(a, psb + (uint32_t)((mi * 16 + lm_row) * 152
                                    + kk * 16 + lm_kch) * 2);
        ldsm_x4_t(bb, vhb + (uint32_t)((kk * 16 + lm_row) * 72
                                       + wn + lm_kch) * 2);
        mma_fp16(oacc[0], a, &bb[0]);
        mma_fp16(oacc[1], a, &bb[2]);
    }

    // --- epilogue: scale by dinv, write fp16 output ---
    {
        const int pr0 = mi * 16 + er;
        const int pr1 = pr0 + 8;
        const float di0 = dinv[pr0];
        const float di1 = dinv[pr1];
        #pragma unroll
        for (int nj = 0; nj < 2; nj++) {
            const int d = wn + nj * 8 + ec;
            size_t o0 = (size_t)(tok0 + (pr0 >> 3)) * AOW
                      + ((size_t)kv * 8 + (pr0 & 7)) * DHEAD + d;
            size_t o1 = (size_t)(tok0 + (pr1 >> 3)) * AOW
                      + ((size_t)kv * 8 + (pr1 & 7)) * DHEAD + d;
            *(__half2*)&out16[o0] =
                __halves2half2(__float2half(oacc[nj][0] * di0),
                               __float2half(oacc[nj][1] * di0));
            *(__half2*)&out16[o1] =
                __halves2half2(__float2half(oacc[nj][2] * di1),
                               __float2half(oacc[nj][3] * di1));
        }
    }
}

// ---------------------------------------------------------------------------
extern "C" void kernel_launch(void* const* d_in, const int* in_sizes, int n_in,
                              void* d_out, int out_size)
{
    const float* hs    = (const float*)d_in[0];
    const float* wqkv  = (const float*)d_in[1];
    const float* wo    = (const float*)d_in[2];
    const float* sinks = (const float*)d_in[3];
    const void*  pos   = (const void*)d_in[4];
    float*       out   = (float*)d_out;

    const int n = in_sizes[0] / HDIM;   // 1024

    __half *qkvh, *ah, *ath, *wq, *wo16, *qb, *kb, *vb;
    cudaGetSymbolAddress((void**)&qkvh, g_qkvh);
    cudaGetSymbolAddress((void**)&ah,   g_ah);
    cudaGetSymbolAddress((void**)&ath,  g_ath);
    cudaGetSymbolAddress((void**)&wq,   g_wq);
    cudaGetSymbolAddress((void**)&wo16, g_wo);
    cudaGetSymbolAddress((void**)&qb,   g_qb);
    cudaGetSymbolAddress((void**)&kb,   g_kb);
    cudaGetSymbolAddress((void**)&vb,   g_vb);

    cudaFuncSetAttribute((const void*)gemm1p_kernel<64, true>,
                         cudaFuncAttributeMaxDynamicSharedMemorySize, SMEM_T64);
    cudaFuncSetAttribute((const void*)gemm1p_kernel<96, false>,
                         cudaFuncAttributeMaxDynamicSharedMemorySize, SMEM_T96);
    cudaFuncSetAttribute((const void*)attn_kernel,
                         cudaFuncAttributeMaxDynamicSharedMemorySize, ATTN_SMEM);

    // 0) positions + RoPE cos/sin table
    {
        int tot = n * 32;
        pos_table_kernel<<<(tot + 255) / 256, 256>>>(pos, n);
    }

    // 1) fused fp16 conversions (8 chunks/thread)
    {
        int n4_hs = (n * HDIM) / 4;
        int n4_wq = (HDIM * QKVW) / 4;
        int n4_wo = (AOW * HDIM) / 4;
        int tot = n4_hs + n4_wq + n4_wo;
        int stride = (tot + 7) / 8;
        cvt_all_kernel<<<(stride + 255) / 256, 256>>>(
            hs, wqkv, wo, ah, wq, wo16, n4_hs, n4_wq, n4_wo, stride);
    }

    // 2) qkv = hs @ Wqkv   (fp16 1-pass, fp16 output)
    {
        dim3 grid(QKVW / 64, n / 128);
        gemm1p_kernel<64, true><<<grid, 128, SMEM_T64>>>(ah, wq, qkvh,
                                                         n, QKVW, HDIM);
    }

    // 3) RoPE -> compact fp16 Q/K/V buffers
    {
        int total = n * (NHEADS + NKV) * 32 + n * NKV * DHEAD / 2;
        rope_kv_kernel<<<(total + 255) / 256, 256>>>(qkvh, qb, kb, vb, n);
    }

    // 4) HMMA attention (4 tokens/block), ex2.f16x2 softmax
    {
        dim3 grid(n / 4, NKV);
        attn_kernel<<<grid, 256, ATTN_SMEM>>>(qb, kb, vb, sinks, ath, n);
    }

    // 5) out = attn @ Wo   (fp16 1-pass, fp32 output, N tile 96 single wave)
    {
        dim3 grid(HDIM / 96, n / 128);
        gemm1p_kernel<96, false><<<grid, 192, SMEM_T96>>>(ath, wo16, out,
                                                          n, HDIM, AOW);
    }
}